// round 15
// baseline (speedup 1.0000x reference)
#include <cuda_runtime.h>
#include <cuda_fp16.h>
#include <cstdint>

// Problem constants (fixed by the dataset)
#define IN_F   4096
#define OUT_F  4096
#define RANK   64
#define M_TOK  8192
#define SCALING 2.0f

// ---------------------------------------------------------------------------
// Device scratch: f16 versions of x and W_eff
// ---------------------------------------------------------------------------
__device__ __half g_xf[(size_t)M_TOK * IN_F];
__device__ __half g_wf[(size_t)OUT_F * IN_F];

// ---------------------------------------------------------------------------
// Helpers
// ---------------------------------------------------------------------------
__device__ __forceinline__ uint32_t smem_to_u32(const void* p) {
    uint32_t a;
    asm("{ .reg .u64 t; cvta.to.shared.u64 t, %1; cvt.u32.u64 %0, t; }"
        : "=r"(a) : "l"(p));
    return a;
}

__device__ __forceinline__ void cp16(uint32_t sdst, const void* gsrc) {
    asm volatile("cp.async.cg.shared.global [%0], [%1], 16;"
                 :: "r"(sdst), "l"(gsrc));
}

__device__ __forceinline__ void ldsm4(uint32_t* r, uint32_t addr) {
    asm volatile("ldmatrix.sync.aligned.m8n8.x4.shared.b16 {%0,%1,%2,%3}, [%4];"
                 : "=r"(r[0]), "=r"(r[1]), "=r"(r[2]), "=r"(r[3])
                 : "r"(addr));
}

__device__ __forceinline__ void ldsm4t(uint32_t* r, uint32_t addr) {
    asm volatile("ldmatrix.sync.aligned.m8n8.x4.trans.shared.b16 {%0,%1,%2,%3}, [%4];"
                 : "=r"(r[0]), "=r"(r[1]), "=r"(r[2]), "=r"(r[3])
                 : "r"(addr));
}

__device__ __forceinline__ void mma_f16(float* c, const uint32_t* a,
                                        uint32_t b0, uint32_t b1) {
    asm volatile(
        "mma.sync.aligned.m16n8k16.row.col.f32.f16.f16.f32 "
        "{%0,%1,%2,%3}, {%4,%5,%6,%7}, {%8,%9}, {%0,%1,%2,%3};"
        : "+f"(c[0]), "+f"(c[1]), "+f"(c[2]), "+f"(c[3])
        : "r"(a[0]), "r"(a[1]), "r"(a[2]), "r"(a[3]), "r"(b0), "r"(b1));
}

// Streaming store: evict-first in L2 (output is never re-read)
__device__ __forceinline__ void stg_cs_f2(float* p, float a, float b) {
    asm volatile("st.global.cs.v2.f32 [%0], {%1, %2};"
                 :: "l"(p), "f"(a), "f"(b) : "memory");
}

__device__ __forceinline__ uint32_t sw128(uint32_t off) {
    return off ^ ((off >> 3) & 0x70);
}

// ---------------------------------------------------------------------------
// Fused prep kernel:
//   blocks [0, 1024):          W_eff = weight + (P .* 2lam) @ Q -> f16 (MMA)
//   blocks [1024, 1024+4096):  x -> f16 streaming (8 float4 per thread)
// ---------------------------------------------------------------------------
#define WEFF_BLOCKS 1024
#define SPLIT_BLOCKS 4096    // 33.55M floats / 8192 per block

__global__ __launch_bounds__(256)
void prep_kernel(const float* __restrict__ weight,
                 const float* __restrict__ P,
                 const float* __restrict__ Lambda,
                 const float* __restrict__ Q,
                 const unsigned char* __restrict__ mask,
                 const float* __restrict__ x)
{
    const int bid = blockIdx.x;
    const int tid = threadIdx.x;

    if (bid >= WEFF_BLOCKS) {
        // ---- split_x branch: pure streaming, 8 independent float4 loads ----
        const size_t blk_base = (size_t)(bid - WEFF_BLOCKS) * 8192;
        #pragma unroll
        for (int j = 0; j < 8; j++) {
            const size_t i = blk_base + ((size_t)j * 256 + tid) * 4;
            float4 v = *reinterpret_cast<const float4*>(x + i);
            *reinterpret_cast<__half2*>(&g_xf[i])     = __floats2half2_rn(v.x, v.y);
            *reinterpret_cast<__half2*>(&g_xf[i + 2]) = __floats2half2_rn(v.z, v.w);
        }
        return;
    }

    // ---- weff branch: one-shot K=64 tensor-core GEMM, 128x128 tile ----
    __shared__ float lam[RANK];
    __shared__ __align__(128) __half sP[128 * 64];    // [m][r], 128B rows, SW128
    __shared__ __align__(128) __half sQ[64 * 128];    // [r][n], 256B rows, swizzled

    const uint32_t pbase = smem_to_u32(sP);
    const uint32_t qbase = smem_to_u32(sQ);

    const int wid = tid >> 5;
    const int lane = tid & 31;
    const int j0 = (bid >> 5) * 128;   // OUT_F rows
    const int n0 = (bid & 31) * 128;   // IN_F cols

    if (tid < RANK)
        lam[tid] = SCALING * Lambda[tid] * (mask[tid] ? 1.0f : 0.0f);
    __syncthreads();

    // Stage P tile [128 m][64 r] fp32 -> f16 (lam folded in). 2048 float4 slots.
    #pragma unroll
    for (int i = 0; i < 8; i++) {
        const int slot = tid + i * 256;
        const int row = slot >> 4;           // 0..127
        const int c4  = slot & 15;           // 0..15 (float4 index, r = c4*4)
        float4 v = *reinterpret_cast<const float4*>(
            &P[(size_t)(j0 + row) * RANK + c4 * 4]);
        __half2 h01 = __floats2half2_rn(v.x * lam[c4 * 4 + 0], v.y * lam[c4 * 4 + 1]);
        __half2 h23 = __floats2half2_rn(v.z * lam[c4 * 4 + 2], v.w * lam[c4 * 4 + 3]);
        const uint32_t off = sw128((uint32_t)(row * 128 + c4 * 8));
        *reinterpret_cast<__half2*>((char*)sP + off)     = h01;
        *reinterpret_cast<__half2*>((char*)sP + off + 4) = h23;
    }

    // Stage Q tile [64 r][128 n] fp32 -> f16, natural layout (coalesced).
    #pragma unroll
    for (int i = 0; i < 8; i++) {
        const int slot = tid + i * 256;
        const int r  = slot >> 5;            // 0..63
        const int n4 = slot & 31;            // 0..31 (float4 index, n = n4*4)
        float4 v = *reinterpret_cast<const float4*>(
            &Q[(size_t)r * IN_F + n0 + n4 * 4]);
        __half2 h01 = __floats2half2_rn(v.x, v.y);
        __half2 h23 = __floats2half2_rn(v.z, v.w);
        const uint32_t off = sw128((uint32_t)(r * 256 + n4 * 8));
        *reinterpret_cast<__half2*>((char*)sQ + off)     = h01;
        *reinterpret_cast<__half2*>((char*)sQ + off + 4) = h23;
    }
    __syncthreads();

    const int wm = wid >> 2;           // 0..1  -> 64 rows
    const int wn = wid & 3;            // 0..3  -> 32 cols

    float acc[4][4][4] = {};

    // A-fragment addressing
    const uint32_t a_row = (uint32_t)(wm * 64 + (lane & 15));
    const uint32_t a_kb  = (uint32_t)((lane >> 4) << 4);
    // B-fragment (trans) addressing
    const int mi = lane >> 3;          // matrix index 0..3
    const int rr = lane & 7;
    const uint32_t bt_k = (uint32_t)((mi & 1) * 8 + rr);        // + ks*16
    const uint32_t bt_n = (uint32_t)(wn * 32 + (mi >> 1) * 8);  // + np*16

    #pragma unroll
    for (int ks = 0; ks < 4; ks++) {
        uint32_t af[4][4], bf[2][4];
        #pragma unroll
        for (int mt = 0; mt < 4; mt++) {
            const uint32_t off = sw128((a_row + mt * 16) * 128 + ks * 32 + a_kb);
            ldsm4(af[mt], pbase + off);
        }
        #pragma unroll
        for (int np = 0; np < 2; np++) {
            const uint32_t off = sw128((bt_k + ks * 16) * 256 + (bt_n + np * 16) * 2);
            ldsm4t(bf[np], qbase + off);
        }
        #pragma unroll
        for (int mt = 0; mt < 4; mt++)
            #pragma unroll
            for (int nt = 0; nt < 4; nt++) {
                const int np = nt >> 1;
                const int hb = (nt & 1) * 2;
                mma_f16(acc[mt][nt], af[mt], bf[np][hb], bf[np][hb + 1]);
            }
    }

    // Epilogue: W_eff = weight + delta, convert to f16
    const int r_lo = lane >> 2;
    const int c_lo = (lane & 3) * 2;
    #pragma unroll
    for (int mt = 0; mt < 4; mt++) {
        const size_t row0 = (size_t)(j0 + wm * 64 + mt * 16 + r_lo);
        #pragma unroll
        for (int nt = 0; nt < 4; nt++) {
            const size_t col = (size_t)(n0 + wn * 32 + nt * 8 + c_lo);
            float2 w0 = *reinterpret_cast<const float2*>(&weight[row0 * IN_F + col]);
            float2 w1 = *reinterpret_cast<const float2*>(&weight[(row0 + 8) * IN_F + col]);
            *reinterpret_cast<__half2*>(&g_wf[row0 * IN_F + col]) =
                __floats2half2_rn(w0.x + acc[mt][nt][0], w0.y + acc[mt][nt][1]);
            *reinterpret_cast<__half2*>(&g_wf[(row0 + 8) * IN_F + col]) =
                __floats2half2_rn(w1.x + acc[mt][nt][2], w1.y + acc[mt][nt][3]);
        }
    }
}

// ---------------------------------------------------------------------------
// Kernel C: single f16 GEMM on mma.sync, fp32 accumulation (R10/R14 body)
//   out[M,N] = Xf @ Wf^T
// 128x128 tile, KC=64, 3-stage cp.async ring, 256 threads (8 warps, 2x4),
// 2 CTAs/SM. Prefetch issued in one burst inside the ks=0 MMA shadow.
// Output stores use st.global.cs (evict-first; output is never re-read).
// ---------------------------------------------------------------------------
#define BM 128
#define BN 128
#define KC 64
#define STAGES 3
#define NK (IN_F / KC)                  // 64 k-tiles

#define TILE_B (128 * 128)               // 16 KB: 128 rows x 128B (KC f16)
#define A_OFF 0
#define B_OFF TILE_B
#define STAGE_B (2 * TILE_B)             // 32 KB
#define GEMM_SMEM (STAGES * STAGE_B)     // 96 KB

// 128 rows x 128B (f16, SW128)
__device__ __forceinline__ void load_tile(uint32_t sdst,
                                          const __half* g,
                                          int kt, int tid)
{
    const char* gb = (const char*)g + (size_t)kt * (KC * 2);
    #pragma unroll
    for (int i = 0; i < 4; i++) {
        const int slot = tid + i * 256;          // 0..1023
        const int row = slot >> 3;               // 0..127
        const int c16 = slot & 7;                // 0..7
        const uint32_t off = (uint32_t)(row * 128 + c16 * 16);
        cp16(sdst + sw128(off), gb + (size_t)row * (IN_F * 2) + c16 * 16);
    }
}

__device__ __forceinline__ void load_stage(uint32_t sb,
                                           const __half* gA,
                                           const __half* gB,
                                           int kt, int tid)
{
    load_tile(sb + A_OFF, gA, kt, tid);
    load_tile(sb + B_OFF, gB, kt, tid);
}

__global__ __launch_bounds__(256, 2)
void gemm_kernel(float* __restrict__ out)
{
    extern __shared__ char smem[];
    const uint32_t sbase = smem_to_u32(smem);
    const int tid = threadIdx.x;
    const int wid = tid >> 5;
    const int lane = tid & 31;

    const int n0 = blockIdx.x * BN;
    const int m0 = blockIdx.y * BM;

    const int wm = wid >> 2;           // 0..1  -> 64 rows of M
    const int wn = wid & 3;            // 0..3  -> 32 cols of N

    const __half* gA = g_xf + (size_t)m0 * IN_F;
    const __half* gB = g_wf + (size_t)n0 * IN_F;

    // Prologue: fill STAGES-1 stages
    #pragma unroll
    for (int c = 0; c < STAGES - 1; c++) {
        load_stage(sbase + c * STAGE_B, gA, gB, c, tid);
        asm volatile("cp.async.commit_group;" ::: "memory");
    }

    float acc[4][4][4] = {};   // [mt][nt][frag], fp32 (64 regs)

    // Per-lane fragment addressing (pre-swizzle byte offsets within a tile)
    const uint32_t a_row = (uint32_t)(wm * 64 + (lane & 15));
    const uint32_t a_kb  = (uint32_t)((lane >> 4) << 4);
    const uint32_t b_row = (uint32_t)(wn * 32 + ((lane & 16) >> 1) + (lane & 7));
    const uint32_t b_kb  = (uint32_t)((lane & 8) << 1);

    for (int kt = 0; kt < NK; kt++) {
        asm volatile("cp.async.wait_group %0;" :: "n"(STAGES - 2) : "memory");
        __syncthreads();

        const uint32_t sb = sbase + (kt % STAGES) * STAGE_B;

        // ---- ks = 0: load fragments and start MMAs immediately ----
        {
            uint32_t af[4][4], bf[2][4];
            #pragma unroll
            for (int mt = 0; mt < 4; mt++) {
                const uint32_t off = sw128((a_row + mt * 16) * 128 + a_kb);
                ldsm4(af[mt], sb + A_OFF + off);
            }
            #pragma unroll
            for (int np = 0; np < 2; np++) {
                const uint32_t off = sw128((b_row + np * 16) * 128 + b_kb);
                ldsm4(bf[np], sb + B_OFF + off);
            }
            #pragma unroll
            for (int mt = 0; mt < 4; mt++)
                #pragma unroll
                for (int nt = 0; nt < 4; nt++) {
                    const int np = nt >> 1;
                    const int hb = (nt & 1) * 2;
                    mma_f16(acc[mt][nt], af[mt], bf[np][hb], bf[np][hb + 1]);
                }
        }

        // ---- Prefetch issue hidden in the tensor-busy shadow of ks=0 ----
        if (kt + STAGES - 1 < NK) {
            load_stage(sbase + ((kt + STAGES - 1) % STAGES) * STAGE_B,
                       gA, gB, kt + STAGES - 1, tid);
        }
        asm volatile("cp.async.commit_group;" ::: "memory");

        // ---- ks = 1..3 ----
        #pragma unroll
        for (int ks = 1; ks < 4; ks++) {
            uint32_t af[4][4], bf[2][4];
            #pragma unroll
            for (int mt = 0; mt < 4; mt++) {
                const uint32_t off = sw128((a_row + mt * 16) * 128 + ks * 32 + a_kb);
                ldsm4(af[mt], sb + A_OFF + off);
            }
            #pragma unroll
            for (int np = 0; np < 2; np++) {
                const uint32_t off = sw128((b_row + np * 16) * 128 + ks * 32 + b_kb);
                ldsm4(bf[np], sb + B_OFF + off);
            }
            #pragma unroll
            for (int mt = 0; mt < 4; mt++)
                #pragma unroll
                for (int nt = 0; nt < 4; nt++) {
                    const int np = nt >> 1;
                    const int hb = (nt & 1) * 2;
                    mma_f16(acc[mt][nt], af[mt], bf[np][hb], bf[np][hb + 1]);
                }
        }
    }

    // Epilogue: streaming fp32 stores (evict-first; never re-read)
    const int r_lo = lane >> 2;
    const int c_lo = (lane & 3) * 2;
    #pragma unroll
    for (int mt = 0; mt < 4; mt++) {
        const size_t row0 = (size_t)(m0 + wm * 64 + mt * 16 + r_lo);
        #pragma unroll
        for (int nt = 0; nt < 4; nt++) {
            const size_t col = (size_t)(n0 + wn * 32 + nt * 8 + c_lo);
            stg_cs_f2(out + row0 * OUT_F + col,
                      acc[mt][nt][0], acc[mt][nt][1]);
            stg_cs_f2(out + (row0 + 8) * OUT_F + col,
                      acc[mt][nt][2], acc[mt][nt][3]);
        }
    }
}

// ---------------------------------------------------------------------------
// Launch.  Inputs: 0=x, 1=weight, 2=P, 3=Lambda, 4=Q, 5=rank_mask
// ---------------------------------------------------------------------------
extern "C" void kernel_launch(void* const* d_in, const int* in_sizes, int n_in,
                              void* d_out, int out_size)
{
    const float* x      = (const float*)d_in[0];
    const float* weight = (const float*)d_in[1];
    const float* P      = (const float*)d_in[2];
    const float* Lambda = (const float*)d_in[3];
    const float* Q      = (const float*)d_in[4];
    const unsigned char* mask = (const unsigned char*)d_in[5];
    float* out = (float*)d_out;

    cudaFuncSetAttribute(gemm_kernel,
                         cudaFuncAttributeMaxDynamicSharedMemorySize, GEMM_SMEM);

    // A+B fused: W_eff -> f16 (tensor-core) and x -> f16 (streaming)
    {
        prep_kernel<<<WEFF_BLOCKS + SPLIT_BLOCKS, 256>>>(weight, P, Lambda, Q, mask, x);
    }
    // C: single f16 tensor-core GEMM, 128x128 tiles, 2 CTAs/SM
    {
        dim3 grid(OUT_F / BN, M_TOK / BM);
        gemm_kernel<<<grid, 256, GEMM_SMEM>>>(out);
    }
}

// round 16
// speedup vs baseline: 1.0217x; 1.0217x over previous
#include <cuda_runtime.h>
#include <cuda_fp16.h>
#include <cstdint>

// Problem constants (fixed by the dataset)
#define IN_F   4096
#define OUT_F  4096
#define RANK   64
#define M_TOK  8192
#define SCALING 2.0f

// ---------------------------------------------------------------------------
// Device scratch: f16 versions of x and W_eff
// ---------------------------------------------------------------------------
__device__ __half g_xf[(size_t)M_TOK * IN_F];
__device__ __half g_wf[(size_t)OUT_F * IN_F];

// ---------------------------------------------------------------------------
// Helpers
// ---------------------------------------------------------------------------
__device__ __forceinline__ uint32_t smem_to_u32(const void* p) {
    uint32_t a;
    asm("{ .reg .u64 t; cvta.to.shared.u64 t, %1; cvt.u32.u64 %0, t; }"
        : "=r"(a) : "l"(p));
    return a;
}

__device__ __forceinline__ void cp16(uint32_t sdst, const void* gsrc) {
    asm volatile("cp.async.cg.shared.global [%0], [%1], 16;"
                 :: "r"(sdst), "l"(gsrc));
}

__device__ __forceinline__ void ldsm4(uint32_t* r, uint32_t addr) {
    asm volatile("ldmatrix.sync.aligned.m8n8.x4.shared.b16 {%0,%1,%2,%3}, [%4];"
                 : "=r"(r[0]), "=r"(r[1]), "=r"(r[2]), "=r"(r[3])
                 : "r"(addr));
}

__device__ __forceinline__ void ldsm4t(uint32_t* r, uint32_t addr) {
    asm volatile("ldmatrix.sync.aligned.m8n8.x4.trans.shared.b16 {%0,%1,%2,%3}, [%4];"
                 : "=r"(r[0]), "=r"(r[1]), "=r"(r[2]), "=r"(r[3])
                 : "r"(addr));
}

__device__ __forceinline__ void mma_f16(float* c, const uint32_t* a,
                                        uint32_t b0, uint32_t b1) {
    asm volatile(
        "mma.sync.aligned.m16n8k16.row.col.f32.f16.f16.f32 "
        "{%0,%1,%2,%3}, {%4,%5,%6,%7}, {%8,%9}, {%0,%1,%2,%3};"
        : "+f"(c[0]), "+f"(c[1]), "+f"(c[2]), "+f"(c[3])
        : "r"(a[0]), "r"(a[1]), "r"(a[2]), "r"(a[3]), "r"(b0), "r"(b1));
}

// Streaming store: evict-first in L2 (output is never re-read)
__device__ __forceinline__ void stg_cs_f2(float* p, float a, float b) {
    asm volatile("st.global.cs.v2.f32 [%0], {%1, %2};"
                 :: "l"(p), "f"(a), "f"(b) : "memory");
}

__device__ __forceinline__ uint32_t sw128(uint32_t off) {
    return off ^ ((off >> 3) & 0x70);
}

// ---------------------------------------------------------------------------
// Fused prep kernel:
//   blocks [0, 1024):          W_eff = weight + (P .* 2lam) @ Q -> f16 (MMA)
//   blocks [1024, 1024+4096):  x -> f16 streaming (8 float4 per thread)
// ---------------------------------------------------------------------------
#define WEFF_BLOCKS 1024
#define SPLIT_BLOCKS 4096    // 33.55M floats / 8192 per block

__global__ __launch_bounds__(256)
void prep_kernel(const float* __restrict__ weight,
                 const float* __restrict__ P,
                 const float* __restrict__ Lambda,
                 const float* __restrict__ Q,
                 const unsigned char* __restrict__ mask,
                 const float* __restrict__ x)
{
    const int bid = blockIdx.x;
    const int tid = threadIdx.x;

    if (bid >= WEFF_BLOCKS) {
        // ---- split_x branch: pure streaming, 8 independent float4 loads ----
        const size_t blk_base = (size_t)(bid - WEFF_BLOCKS) * 8192;
        #pragma unroll
        for (int j = 0; j < 8; j++) {
            const size_t i = blk_base + ((size_t)j * 256 + tid) * 4;
            float4 v = *reinterpret_cast<const float4*>(x + i);
            *reinterpret_cast<__half2*>(&g_xf[i])     = __floats2half2_rn(v.x, v.y);
            *reinterpret_cast<__half2*>(&g_xf[i + 2]) = __floats2half2_rn(v.z, v.w);
        }
        return;
    }

    // ---- weff branch: one-shot K=64 tensor-core GEMM, 128x128 tile ----
    __shared__ float lam[RANK];
    __shared__ __align__(128) __half sP[128 * 64];    // [m][r], 128B rows, SW128
    __shared__ __align__(128) __half sQ[64 * 128];    // [r][n], 256B rows, swizzled

    const uint32_t pbase = smem_to_u32(sP);
    const uint32_t qbase = smem_to_u32(sQ);

    const int wid = tid >> 5;
    const int lane = tid & 31;
    const int j0 = (bid >> 5) * 128;   // OUT_F rows
    const int n0 = (bid & 31) * 128;   // IN_F cols

    if (tid < RANK)
        lam[tid] = SCALING * Lambda[tid] * (mask[tid] ? 1.0f : 0.0f);
    __syncthreads();

    // Stage P tile [128 m][64 r] fp32 -> f16 (lam folded in). 2048 float4 slots.
    #pragma unroll
    for (int i = 0; i < 8; i++) {
        const int slot = tid + i * 256;
        const int row = slot >> 4;           // 0..127
        const int c4  = slot & 15;           // 0..15 (float4 index, r = c4*4)
        float4 v = *reinterpret_cast<const float4*>(
            &P[(size_t)(j0 + row) * RANK + c4 * 4]);
        __half2 h01 = __floats2half2_rn(v.x * lam[c4 * 4 + 0], v.y * lam[c4 * 4 + 1]);
        __half2 h23 = __floats2half2_rn(v.z * lam[c4 * 4 + 2], v.w * lam[c4 * 4 + 3]);
        const uint32_t off = sw128((uint32_t)(row * 128 + c4 * 8));
        *reinterpret_cast<__half2*>((char*)sP + off)     = h01;
        *reinterpret_cast<__half2*>((char*)sP + off + 4) = h23;
    }

    // Stage Q tile [64 r][128 n] fp32 -> f16, natural layout (coalesced).
    #pragma unroll
    for (int i = 0; i < 8; i++) {
        const int slot = tid + i * 256;
        const int r  = slot >> 5;            // 0..63
        const int n4 = slot & 31;            // 0..31 (float4 index, n = n4*4)
        float4 v = *reinterpret_cast<const float4*>(
            &Q[(size_t)r * IN_F + n0 + n4 * 4]);
        __half2 h01 = __floats2half2_rn(v.x, v.y);
        __half2 h23 = __floats2half2_rn(v.z, v.w);
        const uint32_t off = sw128((uint32_t)(r * 256 + n4 * 8));
        *reinterpret_cast<__half2*>((char*)sQ + off)     = h01;
        *reinterpret_cast<__half2*>((char*)sQ + off + 4) = h23;
    }
    __syncthreads();

    const int wm = wid >> 2;           // 0..1  -> 64 rows
    const int wn = wid & 3;            // 0..3  -> 32 cols

    float acc[4][4][4] = {};

    // A-fragment addressing
    const uint32_t a_row = (uint32_t)(wm * 64 + (lane & 15));
    const uint32_t a_kb  = (uint32_t)((lane >> 4) << 4);
    // B-fragment (trans) addressing
    const int mi = lane >> 3;          // matrix index 0..3
    const int rr = lane & 7;
    const uint32_t bt_k = (uint32_t)((mi & 1) * 8 + rr);        // + ks*16
    const uint32_t bt_n = (uint32_t)(wn * 32 + (mi >> 1) * 8);  // + np*16

    #pragma unroll
    for (int ks = 0; ks < 4; ks++) {
        uint32_t af[4][4], bf[2][4];
        #pragma unroll
        for (int mt = 0; mt < 4; mt++) {
            const uint32_t off = sw128((a_row + mt * 16) * 128 + ks * 32 + a_kb);
            ldsm4(af[mt], pbase + off);
        }
        #pragma unroll
        for (int np = 0; np < 2; np++) {
            const uint32_t off = sw128((bt_k + ks * 16) * 256 + (bt_n + np * 16) * 2);
            ldsm4t(bf[np], qbase + off);
        }
        #pragma unroll
        for (int mt = 0; mt < 4; mt++)
            #pragma unroll
            for (int nt = 0; nt < 4; nt++) {
                const int np = nt >> 1;
                const int hb = (nt & 1) * 2;
                mma_f16(acc[mt][nt], af[mt], bf[np][hb], bf[np][hb + 1]);
            }
    }

    // Epilogue: W_eff = weight + delta, convert to f16
    const int r_lo = lane >> 2;
    const int c_lo = (lane & 3) * 2;
    #pragma unroll
    for (int mt = 0; mt < 4; mt++) {
        const size_t row0 = (size_t)(j0 + wm * 64 + mt * 16 + r_lo);
        #pragma unroll
        for (int nt = 0; nt < 4; nt++) {
            const size_t col = (size_t)(n0 + wn * 32 + nt * 8 + c_lo);
            float2 w0 = *reinterpret_cast<const float2*>(&weight[row0 * IN_F + col]);
            float2 w1 = *reinterpret_cast<const float2*>(&weight[(row0 + 8) * IN_F + col]);
            *reinterpret_cast<__half2*>(&g_wf[row0 * IN_F + col]) =
                __floats2half2_rn(w0.x + acc[mt][nt][0], w0.y + acc[mt][nt][1]);
            *reinterpret_cast<__half2*>(&g_wf[(row0 + 8) * IN_F + col]) =
                __floats2half2_rn(w1.x + acc[mt][nt][2], w1.y + acc[mt][nt][3]);
        }
    }
}

// ---------------------------------------------------------------------------
// Kernel C: single f16 GEMM on mma.sync, fp32 accumulation
//   out[M,N] = Xf @ Wf^T
// 128x128 tile, KC=64, 3-stage cp.async ring, 128 threads (4 warps, 2x2),
// warp tile 64x64, 2 CTAs/SM. A and B each read only 2x from SMEM
// (vs 4x/2x with 8 warps) -> smem-read cycles drop to 75% of tensor cycles.
// Prefetch issued in one burst inside the ks=0 MMA shadow (R10 trick).
// ---------------------------------------------------------------------------
#define BM 128
#define BN 128
#define KC 64
#define STAGES 3
#define NK (IN_F / KC)                  // 64 k-tiles
#define GTHR 128

#define TILE_B (128 * 128)               // 16 KB: 128 rows x 128B (KC f16)
#define A_OFF 0
#define B_OFF TILE_B
#define STAGE_B (2 * TILE_B)             // 32 KB
#define GEMM_SMEM (STAGES * STAGE_B)     // 96 KB

// 128 rows x 128B (f16, SW128), 128 threads cooperative
__device__ __forceinline__ void load_tile(uint32_t sdst,
                                          const __half* g,
                                          int kt, int tid)
{
    const char* gb = (const char*)g + (size_t)kt * (KC * 2);
    #pragma unroll
    for (int i = 0; i < 8; i++) {
        const int slot = tid + i * GTHR;         // 0..1023
        const int row = slot >> 3;               // 0..127
        const int c16 = slot & 7;                // 0..7
        const uint32_t off = (uint32_t)(row * 128 + c16 * 16);
        cp16(sdst + sw128(off), gb + (size_t)row * (IN_F * 2) + c16 * 16);
    }
}

__device__ __forceinline__ void load_stage(uint32_t sb,
                                           const __half* gA,
                                           const __half* gB,
                                           int kt, int tid)
{
    load_tile(sb + A_OFF, gA, kt, tid);
    load_tile(sb + B_OFF, gB, kt, tid);
}

__global__ __launch_bounds__(GTHR, 2)
void gemm_kernel(float* __restrict__ out)
{
    extern __shared__ char smem[];
    const uint32_t sbase = smem_to_u32(smem);
    const int tid = threadIdx.x;
    const int wid = tid >> 5;          // 0..3
    const int lane = tid & 31;

    const int n0 = blockIdx.x * BN;
    const int m0 = blockIdx.y * BM;

    const int wm = wid >> 1;           // 0..1  -> 64 rows of M
    const int wn = wid & 1;            // 0..1  -> 64 cols of N

    const __half* gA = g_xf + (size_t)m0 * IN_F;
    const __half* gB = g_wf + (size_t)n0 * IN_F;

    // Prologue: fill STAGES-1 stages
    #pragma unroll
    for (int c = 0; c < STAGES - 1; c++) {
        load_stage(sbase + c * STAGE_B, gA, gB, c, tid);
        asm volatile("cp.async.commit_group;" ::: "memory");
    }

    float acc[4][8][4] = {};   // [mt][nt][frag], fp32 (128 regs)

    // Per-lane fragment addressing (pre-swizzle byte offsets within a tile)
    const uint32_t a_row = (uint32_t)(wm * 64 + (lane & 15));
    const uint32_t a_kb  = (uint32_t)((lane >> 4) << 4);
    const uint32_t b_row = (uint32_t)(wn * 64 + ((lane & 16) >> 1) + (lane & 7));
    const uint32_t b_kb  = (uint32_t)((lane & 8) << 1);

    for (int kt = 0; kt < NK; kt++) {
        asm volatile("cp.async.wait_group %0;" :: "n"(STAGES - 2) : "memory");
        __syncthreads();

        const uint32_t sb = sbase + (kt % STAGES) * STAGE_B;

        // ---- ks = 0: load fragments and start MMAs immediately ----
        {
            uint32_t af[4][4], bf[4][4];
            #pragma unroll
            for (int mt = 0; mt < 4; mt++) {
                const uint32_t off = sw128((a_row + mt * 16) * 128 + a_kb);
                ldsm4(af[mt], sb + A_OFF + off);
            }
            #pragma unroll
            for (int np = 0; np < 4; np++) {
                const uint32_t off = sw128((b_row + np * 16) * 128 + b_kb);
                ldsm4(bf[np], sb + B_OFF + off);
            }
            #pragma unroll
            for (int mt = 0; mt < 4; mt++)
                #pragma unroll
                for (int nt = 0; nt < 8; nt++) {
                    const int np = nt >> 1;
                    const int hb = (nt & 1) * 2;
                    mma_f16(acc[mt][nt], af[mt], bf[np][hb], bf[np][hb + 1]);
                }
        }

        // ---- Prefetch issue hidden in the tensor-busy shadow of ks=0 ----
        if (kt + STAGES - 1 < NK) {
            load_stage(sbase + ((kt + STAGES - 1) % STAGES) * STAGE_B,
                       gA, gB, kt + STAGES - 1, tid);
        }
        asm volatile("cp.async.commit_group;" ::: "memory");

        // ---- ks = 1..3 ----
        #pragma unroll
        for (int ks = 1; ks < 4; ks++) {
            uint32_t af[4][4], bf[4][4];
            #pragma unroll
            for (int mt = 0; mt < 4; mt++) {
                const uint32_t off = sw128((a_row + mt * 16) * 128 + ks * 32 + a_kb);
                ldsm4(af[mt], sb + A_OFF + off);
            }
            #pragma unroll
            for (int np = 0; np < 4; np++) {
                const uint32_t off = sw128((b_row + np * 16) * 128 + ks * 32 + b_kb);
                ldsm4(bf[np], sb + B_OFF + off);
            }
            #pragma unroll
            for (int mt = 0; mt < 4; mt++)
                #pragma unroll
                for (int nt = 0; nt < 8; nt++) {
                    const int np = nt >> 1;
                    const int hb = (nt & 1) * 2;
                    mma_f16(acc[mt][nt], af[mt], bf[np][hb], bf[np][hb + 1]);
                }
        }
    }

    // Epilogue: streaming fp32 stores (evict-first; never re-read)
    const int r_lo = lane >> 2;
    const int c_lo = (lane & 3) * 2;
    #pragma unroll
    for (int mt = 0; mt < 4; mt++) {
        const size_t row0 = (size_t)(m0 + wm * 64 + mt * 16 + r_lo);
        #pragma unroll
        for (int nt = 0; nt < 8; nt++) {
            const size_t col = (size_t)(n0 + wn * 64 + nt * 8 + c_lo);
            stg_cs_f2(out + row0 * OUT_F + col,
                      acc[mt][nt][0], acc[mt][nt][1]);
            stg_cs_f2(out + (row0 + 8) * OUT_F + col,
                      acc[mt][nt][2], acc[mt][nt][3]);
        }
    }
}

// ---------------------------------------------------------------------------
// Launch.  Inputs: 0=x, 1=weight, 2=P, 3=Lambda, 4=Q, 5=rank_mask
// ---------------------------------------------------------------------------
extern "C" void kernel_launch(void* const* d_in, const int* in_sizes, int n_in,
                              void* d_out, int out_size)
{
    const float* x      = (const float*)d_in[0];
    const float* weight = (const float*)d_in[1];
    const float* P      = (const float*)d_in[2];
    const float* Lambda = (const float*)d_in[3];
    const float* Q      = (const float*)d_in[4];
    const unsigned char* mask = (const unsigned char*)d_in[5];
    float* out = (float*)d_out;

    cudaFuncSetAttribute(gemm_kernel,
                         cudaFuncAttributeMaxDynamicSharedMemorySize, GEMM_SMEM);

    // A+B fused: W_eff -> f16 (tensor-core) and x -> f16 (streaming)
    {
        prep_kernel<<<WEFF_BLOCKS + SPLIT_BLOCKS, 256>>>(weight, P, Lambda, Q, mask, x);
    }
    // C: single f16 tensor-core GEMM, 128x128 tiles, 64x64 warp tiles
    {
        dim3 grid(OUT_F / BN, M_TOK / BM);
        gemm_kernel<<<grid, GTHR, GEMM_SMEM>>>(out);
    }
}